// round 1
// baseline (speedup 1.0000x reference)
#include <cuda_runtime.h>
#include <cuda_bf16.h>
#include <math.h>

// Problem constants
#define BATCH   2
#define SEQ     4096
#define DMODEL  768
#define NHEADS  12
#define DK      64
#define MROWS   (BATCH * SEQ)          // 8192

// Scratch: Q, K, V, context in [B*S, DMODEL] layout (head h occupies cols h*64..h*64+63)
__device__ float g_q[MROWS * DMODEL];
__device__ float g_k[MROWS * DMODEL];
__device__ float g_v[MROWS * DMODEL];
__device__ float g_ctx[MROWS * DMODEL];

// ---------------------------------------------------------------------------
// GEMM: C[M,N] = A[M,K] @ W[N,K]^T + bias[N]
// Tile 128x128, BK=8, 256 threads, 8x8 microtile, smem stored k-major
// (As[k][i], Bs[k][j]) so inner loads are float4.
// ---------------------------------------------------------------------------
__global__ void __launch_bounds__(256)
gemm_bias_kernel(const float* __restrict__ A,
                 const float* __restrict__ W,
                 const float* __restrict__ bias,
                 float* __restrict__ C,
                 int M, int N, int K)
{
    __shared__ float As[8 * 128];
    __shared__ float Bs[8 * 128];

    const int tid = threadIdx.x;
    const int bx = blockIdx.x;      // N tile
    const int by = blockIdx.y;      // M tile
    const int tr = tid >> 4;        // 0..15
    const int tc = tid & 15;        // 0..15

    // Cooperative load mapping: each thread loads one float4 of A and one of W
    const int lr = tid >> 1;            // 0..127 (tile row)
    const int lc = (tid & 1) * 4;       // k offset 0 or 4

    const float* Ag = A + (size_t)(by * 128 + lr) * K + lc;
    const float* Wg = W + (size_t)(bx * 128 + lr) * K + lc;

    float acc[8][8];
#pragma unroll
    for (int i = 0; i < 8; i++)
#pragma unroll
        for (int j = 0; j < 8; j++) acc[i][j] = 0.0f;

    for (int kt = 0; kt < K; kt += 8) {
        float4 av = *(const float4*)(Ag + kt);
        float4 wv = *(const float4*)(Wg + kt);
        As[(lc + 0) * 128 + lr] = av.x;
        As[(lc + 1) * 128 + lr] = av.y;
        As[(lc + 2) * 128 + lr] = av.z;
        As[(lc + 3) * 128 + lr] = av.w;
        Bs[(lc + 0) * 128 + lr] = wv.x;
        Bs[(lc + 1) * 128 + lr] = wv.y;
        Bs[(lc + 2) * 128 + lr] = wv.z;
        Bs[(lc + 3) * 128 + lr] = wv.w;
        __syncthreads();

#pragma unroll
        for (int kk = 0; kk < 8; kk++) {
            float a[8], b[8];
            *(float4*)(a)     = *(float4*)&As[kk * 128 + tr * 8];
            *(float4*)(a + 4) = *(float4*)&As[kk * 128 + tr * 8 + 4];
            *(float4*)(b)     = *(float4*)&Bs[kk * 128 + tc * 8];
            *(float4*)(b + 4) = *(float4*)&Bs[kk * 128 + tc * 8 + 4];
#pragma unroll
            for (int i = 0; i < 8; i++)
#pragma unroll
                for (int j = 0; j < 8; j++)
                    acc[i][j] = fmaf(a[i], b[j], acc[i][j]);
        }
        __syncthreads();
    }

    const int row0 = by * 128 + tr * 8;
    const int col0 = bx * 128 + tc * 8;
    float bv[8];
    *(float4*)(bv)     = *(const float4*)&bias[col0];
    *(float4*)(bv + 4) = *(const float4*)&bias[col0 + 4];

#pragma unroll
    for (int i = 0; i < 8; i++) {
        float4 o1, o2;
        o1.x = acc[i][0] + bv[0]; o1.y = acc[i][1] + bv[1];
        o1.z = acc[i][2] + bv[2]; o1.w = acc[i][3] + bv[3];
        o2.x = acc[i][4] + bv[4]; o2.y = acc[i][5] + bv[5];
        o2.z = acc[i][6] + bv[6]; o2.w = acc[i][7] + bv[7];
        float* crow = C + (size_t)(row0 + i) * N + col0;
        *(float4*)(crow)     = o1;
        *(float4*)(crow + 4) = o2;
    }
}

// ---------------------------------------------------------------------------
// Flash attention, fp32. One block per (query-tile of 64, head, batch).
// 256 threads, thread grid 16x16, 4x4 microtile over the 64x64 score tile.
// Smem: Qt[d][i], KPt[d][j] (K^T, reused as P^T[j][i]), Vs[j][d].
// Online softmax with per-row (m, l) kept redundantly in the 16 threads of a
// row group; reductions via __shfl_xor within the 16-lane half-warp.
// ---------------------------------------------------------------------------
__global__ void __launch_bounds__(256)
attn_kernel(const float* __restrict__ Q,
            const float* __restrict__ K,
            const float* __restrict__ V,
            float* __restrict__ O)
{
    extern __shared__ float sm[];
    float* Qt  = sm;            // [64][64] Qt[d*64 + i]
    float* KPt = sm + 4096;     // [64][64] Kt[d*64 + j] -> Pt[j*64 + i]
    float* Vs  = sm + 8192;     // [64][64] Vs[j*64 + d]

    const int b = blockIdx.z;
    const int h = blockIdx.y;
    const int q0 = blockIdx.x * 64;
    const int tid = threadIdx.x;
    const int tr = tid >> 4;          // 0..15 (row group)
    const int tc = tid & 15;          // 0..15 (col group)
    const int i0 = tr * 4;
    const int j0 = tc * 4;

    const size_t bh = (size_t)b * SEQ * DMODEL + (size_t)h * DK;
    const float* Qg = Q + bh;
    const float* Kg = K + bh;
    const float* Vg = V + bh;
    float* Og = O + bh;

    // Cooperative load mapping: thread handles row lr (0..63), 16 cols at lc
    const int lr = tid >> 2;
    const int lc = (tid & 3) * 16;

    // Load Q tile transposed (once)
    {
        const float* qrow = Qg + (size_t)(q0 + lr) * DMODEL + lc;
#pragma unroll
        for (int u = 0; u < 16; u += 4) {
            float4 v = *(const float4*)(qrow + u);
            Qt[(lc + u + 0) * 64 + lr] = v.x;
            Qt[(lc + u + 1) * 64 + lr] = v.y;
            Qt[(lc + u + 2) * 64 + lr] = v.z;
            Qt[(lc + u + 3) * 64 + lr] = v.w;
        }
    }

    float m[4], l[4], o[4][4];
#pragma unroll
    for (int i = 0; i < 4; i++) {
        m[i] = -INFINITY;
        l[i] = 0.0f;
#pragma unroll
        for (int c = 0; c < 4; c++) o[i][c] = 0.0f;
    }

    for (int t0 = 0; t0 < SEQ; t0 += 64) {
        __syncthreads();   // prior PV reads of KPt/Vs done
        // Load K tile transposed + V tile row-major
        {
            const float* krow = Kg + (size_t)(t0 + lr) * DMODEL + lc;
#pragma unroll
            for (int u = 0; u < 16; u += 4) {
                float4 v = *(const float4*)(krow + u);
                KPt[(lc + u + 0) * 64 + lr] = v.x;
                KPt[(lc + u + 1) * 64 + lr] = v.y;
                KPt[(lc + u + 2) * 64 + lr] = v.z;
                KPt[(lc + u + 3) * 64 + lr] = v.w;
            }
            const float* vrow = Vg + (size_t)(t0 + lr) * DMODEL + lc;
#pragma unroll
            for (int u = 0; u < 16; u += 4) {
                *(float4*)&Vs[lr * 64 + lc + u] = *(const float4*)(vrow + u);
            }
        }
        __syncthreads();

        // S = Q @ K^T (per-thread 4x4)
        float s[4][4];
#pragma unroll
        for (int i = 0; i < 4; i++)
#pragma unroll
            for (int j = 0; j < 4; j++) s[i][j] = 0.0f;

#pragma unroll 16
        for (int d = 0; d < 64; d++) {
            float4 qv = *(float4*)&Qt[d * 64 + i0];
            float4 kv = *(float4*)&KPt[d * 64 + j0];
            float qa[4] = {qv.x, qv.y, qv.z, qv.w};
            float ka[4] = {kv.x, kv.y, kv.z, kv.w};
#pragma unroll
            for (int i = 0; i < 4; i++)
#pragma unroll
                for (int j = 0; j < 4; j++)
                    s[i][j] = fmaf(qa[i], ka[j], s[i][j]);
        }

        // Online softmax update (row stats across the 16-thread row group)
        float alpha[4];
#pragma unroll
        for (int i = 0; i < 4; i++) {
#pragma unroll
            for (int j = 0; j < 4; j++) s[i][j] *= 0.125f;   // 1/sqrt(64)
            float ml = fmaxf(fmaxf(s[i][0], s[i][1]), fmaxf(s[i][2], s[i][3]));
#pragma unroll
            for (int off = 8; off >= 1; off >>= 1)
                ml = fmaxf(ml, __shfl_xor_sync(0xffffffffu, ml, off));
            float mnew = fmaxf(m[i], ml);
            alpha[i] = __expf(m[i] - mnew);
            float ls = 0.0f;
#pragma unroll
            for (int j = 0; j < 4; j++) {
                s[i][j] = __expf(s[i][j] - mnew);
                ls += s[i][j];
            }
#pragma unroll
            for (int off = 8; off >= 1; off >>= 1)
                ls += __shfl_xor_sync(0xffffffffu, ls, off);
            l[i] = l[i] * alpha[i] + ls;
            m[i] = mnew;
#pragma unroll
            for (int c = 0; c < 4; c++) o[i][c] *= alpha[i];
        }

        __syncthreads();   // everyone done reading Kt before overwriting with Pt
        // Store P transposed: Pt[j][i]
#pragma unroll
        for (int i = 0; i < 4; i++)
#pragma unroll
            for (int j = 0; j < 4; j++)
                KPt[(j0 + j) * 64 + (i0 + i)] = s[i][j];
        __syncthreads();

        // O += P @ V  (thread owns rows i0..i0+3, cols j0..j0+3 of O)
#pragma unroll 16
        for (int j = 0; j < 64; j++) {
            float4 pv = *(float4*)&KPt[j * 64 + i0];
            float4 vv = *(float4*)&Vs[j * 64 + j0];
            float pa[4] = {pv.x, pv.y, pv.z, pv.w};
            float va[4] = {vv.x, vv.y, vv.z, vv.w};
#pragma unroll
            for (int i = 0; i < 4; i++)
#pragma unroll
                for (int c = 0; c < 4; c++)
                    o[i][c] = fmaf(pa[i], va[c], o[i][c]);
        }
    }

    // Epilogue: normalize and store
#pragma unroll
    for (int i = 0; i < 4; i++) {
        float inv = 1.0f / l[i];
        float4 r;
        r.x = o[i][0] * inv;
        r.y = o[i][1] * inv;
        r.z = o[i][2] * inv;
        r.w = o[i][3] * inv;
        *(float4*)&Og[(size_t)(q0 + i0 + i) * DMODEL + j0] = r;
    }
}

// ---------------------------------------------------------------------------
// Launch
// ---------------------------------------------------------------------------
extern "C" void kernel_launch(void* const* d_in, const int* in_sizes, int n_in,
                              void* d_out, int out_size)
{
    const float* x  = (const float*)d_in[0];
    const float* Wq = (const float*)d_in[1];
    const float* bq = (const float*)d_in[2];
    const float* Wk = (const float*)d_in[3];
    const float* bk = (const float*)d_in[4];
    const float* Wv = (const float*)d_in[5];
    const float* bv = (const float*)d_in[6];
    const float* Wo = (const float*)d_in[7];
    const float* bo = (const float*)d_in[8];
    float* out = (float*)d_out;

    float *q, *k, *v, *ctx;
    cudaGetSymbolAddress((void**)&q,   g_q);
    cudaGetSymbolAddress((void**)&k,   g_k);
    cudaGetSymbolAddress((void**)&v,   g_v);
    cudaGetSymbolAddress((void**)&ctx, g_ctx);

    dim3 pgrid(DMODEL / 128, MROWS / 128);   // (6, 64)
    gemm_bias_kernel<<<pgrid, 256>>>(x, Wq, bq, q, MROWS, DMODEL, DMODEL);
    gemm_bias_kernel<<<pgrid, 256>>>(x, Wk, bk, k, MROWS, DMODEL, DMODEL);
    gemm_bias_kernel<<<pgrid, 256>>>(x, Wv, bv, v, MROWS, DMODEL, DMODEL);

    cudaFuncSetAttribute(attn_kernel,
                         cudaFuncAttributeMaxDynamicSharedMemorySize, 49152);
    attn_kernel<<<dim3(SEQ / 64, NHEADS, BATCH), 256, 49152>>>(q, k, v, ctx);

    gemm_bias_kernel<<<pgrid, 256>>>(ctx, Wo, bo, out, MROWS, DMODEL, DMODEL);
}

// round 2
// speedup vs baseline: 3.0472x; 3.0472x over previous
#include <cuda_runtime.h>
#include <cuda_bf16.h>
#include <math.h>

// Problem constants
#define BATCH   2
#define SEQ     4096
#define DMODEL  768
#define NHEADS  12
#define DK      64
#define MROWS   (BATCH * SEQ)          // 8192

// Attention tiling
#define BR      128
#define TC      64
#define QSTRIDE 68     // bank = 4g + t  -> conflict-free A/B frag loads
#define VSTRIDE 72     // bank = 8t + g  -> conflict-free V frag loads

// Scratch buffers
__device__ float g_q[MROWS * DMODEL];
__device__ float g_k[MROWS * DMODEL];
__device__ float g_v[MROWS * DMODEL];
__device__ float g_ctx[MROWS * DMODEL];

// ---------------------------------------------------------------------------
// helpers
// ---------------------------------------------------------------------------
__device__ __forceinline__ unsigned tf32_rna(float x) {
    unsigned r;
    asm("cvt.rna.tf32.f32 %0, %1;" : "=r"(r) : "f"(x));
    return r;
}

__device__ __forceinline__ void mma_tf32(float* d, const unsigned* a,
                                         unsigned b0, unsigned b1) {
    asm volatile(
        "mma.sync.aligned.m16n8k8.row.col.f32.tf32.tf32.f32 "
        "{%0,%1,%2,%3}, {%4,%5,%6,%7}, {%8,%9}, {%0,%1,%2,%3};"
        : "+f"(d[0]), "+f"(d[1]), "+f"(d[2]), "+f"(d[3])
        : "r"(a[0]), "r"(a[1]), "r"(a[2]), "r"(a[3]), "r"(b0), "r"(b1));
}

// ---------------------------------------------------------------------------
// tf32 GEMM: C[M,N] = A[M,K] @ W[N,K]^T + bias[N]
// 128x128 tile, BK=16, 256 threads (8 warps as 2x4), warp = 64x32 via
// 4 m-frags x 4 n-frags of m16n8k8.
// ---------------------------------------------------------------------------
__global__ void __launch_bounds__(256)
gemm_tf32(const float* __restrict__ A, const float* __restrict__ W,
          const float* __restrict__ bias, float* __restrict__ C,
          int M, int N, int K)
{
    __shared__ unsigned As[128 * 20];
    __shared__ unsigned Ws[128 * 20];

    const int tid  = threadIdx.x;
    const int warp = tid >> 5;
    const int lane = tid & 31;
    const int g    = lane >> 2;
    const int t    = lane & 3;
    const int wm   = warp >> 2;          // 0..1
    const int wn   = warp & 3;           // 0..3
    const int bx   = blockIdx.x;
    const int by   = blockIdx.y;

    const int lrow = tid >> 1;
    const int lk   = (tid & 1) * 8;
    const float* Ag = A + (size_t)(by * 128 + lrow) * K + lk;
    const float* Wg = W + (size_t)(bx * 128 + lrow) * K + lk;
    unsigned* as = As + lrow * 20 + lk;
    unsigned* ws = Ws + lrow * 20 + lk;

    float acc[4][4][4];
#pragma unroll
    for (int mi = 0; mi < 4; mi++)
#pragma unroll
        for (int ni = 0; ni < 4; ni++)
#pragma unroll
            for (int e = 0; e < 4; e++) acc[mi][ni][e] = 0.0f;

    for (int kt = 0; kt < K; kt += 16) {
        float4 a0 = *(const float4*)(Ag + kt);
        float4 a1 = *(const float4*)(Ag + kt + 4);
        float4 w0 = *(const float4*)(Wg + kt);
        float4 w1 = *(const float4*)(Wg + kt + 4);
        as[0] = tf32_rna(a0.x); as[1] = tf32_rna(a0.y);
        as[2] = tf32_rna(a0.z); as[3] = tf32_rna(a0.w);
        as[4] = tf32_rna(a1.x); as[5] = tf32_rna(a1.y);
        as[6] = tf32_rna(a1.z); as[7] = tf32_rna(a1.w);
        ws[0] = tf32_rna(w0.x); ws[1] = tf32_rna(w0.y);
        ws[2] = tf32_rna(w0.z); ws[3] = tf32_rna(w0.w);
        ws[4] = tf32_rna(w1.x); ws[5] = tf32_rna(w1.y);
        ws[6] = tf32_rna(w1.z); ws[7] = tf32_rna(w1.w);
        __syncthreads();

#pragma unroll
        for (int kc = 0; kc < 2; kc++) {
            unsigned af[4][4];
#pragma unroll
            for (int mi = 0; mi < 4; mi++) {
                const unsigned* p = As + (wm * 64 + mi * 16 + g) * 20 + kc * 8 + t;
                af[mi][0] = p[0];
                af[mi][1] = p[8 * 20];
                af[mi][2] = p[4];
                af[mi][3] = p[8 * 20 + 4];
            }
#pragma unroll
            for (int ni = 0; ni < 4; ni++) {
                const unsigned* p = Ws + (wn * 32 + ni * 8 + g) * 20 + kc * 8 + t;
                unsigned b0 = p[0];
                unsigned b1 = p[4];
#pragma unroll
                for (int mi = 0; mi < 4; mi++)
                    mma_tf32(acc[mi][ni], af[mi], b0, b1);
            }
        }
        __syncthreads();
    }

    // epilogue
#pragma unroll
    for (int ni = 0; ni < 4; ni++) {
        const int col = bx * 128 + wn * 32 + ni * 8 + 2 * t;
        float2 bv = *(const float2*)&bias[col];
#pragma unroll
        for (int mi = 0; mi < 4; mi++) {
            const int row = by * 128 + wm * 64 + mi * 16 + g;
            float2 r0, r1;
            r0.x = acc[mi][ni][0] + bv.x; r0.y = acc[mi][ni][1] + bv.y;
            r1.x = acc[mi][ni][2] + bv.x; r1.y = acc[mi][ni][3] + bv.y;
            *(float2*)&C[(size_t)row * N + col]       = r0;
            *(float2*)&C[(size_t)(row + 8) * N + col] = r1;
        }
    }
}

// ---------------------------------------------------------------------------
// Flash attention, tf32 mma. Block: BR=128 query rows x (head, batch).
// 8 warps, each owns 16 query rows. KV tiles of 64.
// S = Q K^T via tf32 mma; softmax stats in registers (2 rows/thread);
// P fragment built from S accumulators by register shuffles; O += P V.
// ---------------------------------------------------------------------------
__global__ void __launch_bounds__(256, 2)
attn_kernel(const float* __restrict__ Q,
            const float* __restrict__ K,
            const float* __restrict__ V,
            float* __restrict__ O)
{
    extern __shared__ unsigned smu[];
    unsigned* Qs = smu;                          // [128][QSTRIDE]
    unsigned* Ks = Qs + 128 * QSTRIDE;           // [64][QSTRIDE]
    unsigned* Vs = Ks + 64 * QSTRIDE;            // [64][VSTRIDE]

    const int b    = blockIdx.z;
    const int h    = blockIdx.y;
    const int q0   = blockIdx.x * BR;
    const int tid  = threadIdx.x;
    const int warp = tid >> 5;
    const int lane = tid & 31;
    const int g    = lane >> 2;
    const int t    = lane & 3;
    const int qr   = warp * 16;                  // warp's row base in tile

    const size_t bh = (size_t)b * SEQ * DMODEL + (size_t)h * DK;
    const float* Qg = Q + bh;
    const float* Kg = K + bh;
    const float* Vg = V + bh;
    float* Og = O + bh;

    // Load Q tile (scaled by 1/sqrt(dk), rounded to tf32)
    {
        const int r  = tid >> 1;
        const int c0 = (tid & 1) * 32;
        const float* qrow = Qg + (size_t)(q0 + r) * DMODEL + c0;
        unsigned* qs = Qs + r * QSTRIDE + c0;
#pragma unroll
        for (int u = 0; u < 32; u += 4) {
            float4 v = *(const float4*)(qrow + u);
            qs[u + 0] = tf32_rna(v.x * 0.125f);
            qs[u + 1] = tf32_rna(v.y * 0.125f);
            qs[u + 2] = tf32_rna(v.z * 0.125f);
            qs[u + 3] = tf32_rna(v.w * 0.125f);
        }
    }

    float m0 = -INFINITY, m1 = -INFINITY, l0 = 0.0f, l1 = 0.0f;
    float oacc[8][4];
#pragma unroll
    for (int nc = 0; nc < 8; nc++)
#pragma unroll
        for (int e = 0; e < 4; e++) oacc[nc][e] = 0.0f;

    const int kv_r  = tid >> 2;
    const int kv_c0 = (tid & 3) * 16;

    for (int t0 = 0; t0 < SEQ; t0 += TC) {
        __syncthreads();   // prior-iteration smem reads complete (covers Q on iter 0)
        // Load K, V tiles (tf32)
        {
            const float* krow = Kg + (size_t)(t0 + kv_r) * DMODEL + kv_c0;
            const float* vrow = Vg + (size_t)(t0 + kv_r) * DMODEL + kv_c0;
            unsigned* ks = Ks + kv_r * QSTRIDE + kv_c0;
            unsigned* vs = Vs + kv_r * VSTRIDE + kv_c0;
#pragma unroll
            for (int u = 0; u < 16; u += 4) {
                float4 kv4 = *(const float4*)(krow + u);
                ks[u + 0] = tf32_rna(kv4.x);
                ks[u + 1] = tf32_rna(kv4.y);
                ks[u + 2] = tf32_rna(kv4.z);
                ks[u + 3] = tf32_rna(kv4.w);
                float4 vv4 = *(const float4*)(vrow + u);
                vs[u + 0] = tf32_rna(vv4.x);
                vs[u + 1] = tf32_rna(vv4.y);
                vs[u + 2] = tf32_rna(vv4.z);
                vs[u + 3] = tf32_rna(vv4.w);
            }
        }
        __syncthreads();

        // ---- S = Q K^T ----
        float sacc[8][4];
#pragma unroll
        for (int nc = 0; nc < 8; nc++)
#pragma unroll
            for (int e = 0; e < 4; e++) sacc[nc][e] = 0.0f;

#pragma unroll
        for (int kc = 0; kc < 8; kc++) {
            unsigned a[4];
            const unsigned* qb = Qs + (qr + g) * QSTRIDE + kc * 8 + t;
            a[0] = qb[0];
            a[1] = qb[8 * QSTRIDE];
            a[2] = qb[4];
            a[3] = qb[8 * QSTRIDE + 4];
#pragma unroll
            for (int nc = 0; nc < 8; nc++) {
                const unsigned* kb = Ks + (nc * 8 + g) * QSTRIDE + kc * 8 + t;
                mma_tf32(sacc[nc], a, kb[0], kb[4]);
            }
        }

        // ---- online softmax ----
        float rm0 = -INFINITY, rm1 = -INFINITY;
#pragma unroll
        for (int nc = 0; nc < 8; nc++) {
            rm0 = fmaxf(rm0, fmaxf(sacc[nc][0], sacc[nc][1]));
            rm1 = fmaxf(rm1, fmaxf(sacc[nc][2], sacc[nc][3]));
        }
        rm0 = fmaxf(rm0, __shfl_xor_sync(0xffffffffu, rm0, 1));
        rm0 = fmaxf(rm0, __shfl_xor_sync(0xffffffffu, rm0, 2));
        rm1 = fmaxf(rm1, __shfl_xor_sync(0xffffffffu, rm1, 1));
        rm1 = fmaxf(rm1, __shfl_xor_sync(0xffffffffu, rm1, 2));

        const float mn0 = fmaxf(m0, rm0);
        const float mn1 = fmaxf(m1, rm1);
        const float al0 = __expf(m0 - mn0);
        const float al1 = __expf(m1 - mn1);
        m0 = mn0; m1 = mn1;

        float rs0 = 0.0f, rs1 = 0.0f;
#pragma unroll
        for (int nc = 0; nc < 8; nc++) {
            sacc[nc][0] = __expf(sacc[nc][0] - mn0);
            sacc[nc][1] = __expf(sacc[nc][1] - mn0);
            sacc[nc][2] = __expf(sacc[nc][2] - mn1);
            sacc[nc][3] = __expf(sacc[nc][3] - mn1);
            rs0 += sacc[nc][0] + sacc[nc][1];
            rs1 += sacc[nc][2] + sacc[nc][3];
        }
        rs0 += __shfl_xor_sync(0xffffffffu, rs0, 1);
        rs0 += __shfl_xor_sync(0xffffffffu, rs0, 2);
        rs1 += __shfl_xor_sync(0xffffffffu, rs1, 1);
        rs1 += __shfl_xor_sync(0xffffffffu, rs1, 2);
        l0 = l0 * al0 + rs0;
        l1 = l1 * al1 + rs1;

#pragma unroll
        for (int nc = 0; nc < 8; nc++) {
            oacc[nc][0] *= al0;
            oacc[nc][1] *= al0;
            oacc[nc][2] *= al1;
            oacc[nc][3] *= al1;
        }

        // ---- O += P V ----
        const int src_lo = (lane & ~3) | (t >> 1);
        const int src_hi = src_lo + 2;
        const bool odd = (t & 1);
#pragma unroll
        for (int kc = 0; kc < 8; kc++) {
            // permute S-acc layout (cols 2t,2t+1) -> A-frag layout (cols t, t+4)
            float x0l = __shfl_sync(0xffffffffu, sacc[kc][0], src_lo);
            float x1l = __shfl_sync(0xffffffffu, sacc[kc][1], src_lo);
            float x0h = __shfl_sync(0xffffffffu, sacc[kc][0], src_hi);
            float x1h = __shfl_sync(0xffffffffu, sacc[kc][1], src_hi);
            float y0l = __shfl_sync(0xffffffffu, sacc[kc][2], src_lo);
            float y1l = __shfl_sync(0xffffffffu, sacc[kc][3], src_lo);
            float y0h = __shfl_sync(0xffffffffu, sacc[kc][2], src_hi);
            float y1h = __shfl_sync(0xffffffffu, sacc[kc][3], src_hi);
            unsigned a[4];
            a[0] = tf32_rna(odd ? x1l : x0l);   // (g,    t)
            a[1] = tf32_rna(odd ? y1l : y0l);   // (g+8,  t)
            a[2] = tf32_rna(odd ? x1h : x0h);   // (g,    t+4)
            a[3] = tf32_rna(odd ? y1h : y0h);   // (g+8,  t+4)
#pragma unroll
            for (int nc = 0; nc < 8; nc++) {
                unsigned b0 = Vs[(kc * 8 + t) * VSTRIDE + nc * 8 + g];
                unsigned b1 = Vs[(kc * 8 + t + 4) * VSTRIDE + nc * 8 + g];
                mma_tf32(oacc[nc], a, b0, b1);
            }
        }
    }

    // epilogue: normalize, store
    const float inv0 = 1.0f / l0;
    const float inv1 = 1.0f / l1;
#pragma unroll
    for (int nc = 0; nc < 8; nc++) {
        const int col = nc * 8 + 2 * t;
        float2 r0, r1;
        r0.x = oacc[nc][0] * inv0; r0.y = oacc[nc][1] * inv0;
        r1.x = oacc[nc][2] * inv1; r1.y = oacc[nc][3] * inv1;
        *(float2*)&Og[(size_t)(q0 + qr + g) * DMODEL + col]     = r0;
        *(float2*)&Og[(size_t)(q0 + qr + g + 8) * DMODEL + col] = r1;
    }
}

// ---------------------------------------------------------------------------
// Launch
// ---------------------------------------------------------------------------
extern "C" void kernel_launch(void* const* d_in, const int* in_sizes, int n_in,
                              void* d_out, int out_size)
{
    const float* x  = (const float*)d_in[0];
    const float* Wq = (const float*)d_in[1];
    const float* bq = (const float*)d_in[2];
    const float* Wk = (const float*)d_in[3];
    const float* bk = (const float*)d_in[4];
    const float* Wv = (const float*)d_in[5];
    const float* bv = (const float*)d_in[6];
    const float* Wo = (const float*)d_in[7];
    const float* bo = (const float*)d_in[8];
    float* out = (float*)d_out;

    float *q, *k, *v, *ctx;
    cudaGetSymbolAddress((void**)&q,   g_q);
    cudaGetSymbolAddress((void**)&k,   g_k);
    cudaGetSymbolAddress((void**)&v,   g_v);
    cudaGetSymbolAddress((void**)&ctx, g_ctx);

    dim3 pgrid(DMODEL / 128, MROWS / 128);   // (6, 64)
    gemm_tf32<<<pgrid, 256>>>(x, Wq, bq, q, MROWS, DMODEL, DMODEL);
    gemm_tf32<<<pgrid, 256>>>(x, Wk, bk, k, MROWS, DMODEL, DMODEL);
    gemm_tf32<<<pgrid, 256>>>(x, Wv, bv, v, MROWS, DMODEL, DMODEL);

    const int attn_smem = (128 * QSTRIDE + 64 * QSTRIDE + 64 * VSTRIDE) * 4;
    cudaFuncSetAttribute(attn_kernel,
                         cudaFuncAttributeMaxDynamicSharedMemorySize, attn_smem);
    attn_kernel<<<dim3(SEQ / BR, NHEADS, BATCH), 256, attn_smem>>>(q, k, v, ctx);

    gemm_tf32<<<pgrid, 256>>>(ctx, Wo, bo, out, MROWS, DMODEL, DMODEL);
}